// round 13
// baseline (speedup 1.0000x reference)
#include <cuda_runtime.h>
#include <cuda_fp16.h>
#include <cstdint>
#include <math.h>

#define HH 4096

// ---------------- scratch ----------------
__device__ __half g_S[256 * 2048];          //  1 MB  fragA order, K=2048
__device__ __half g_Wcat[4096 * 2048];      // 16 MB  fragA order, K=2048
__device__ __half g_W1tA[4096 * 2048];      // 16 MB  fragB order, K=2048 (d<2048)
__device__ __half g_W1tB[4096 * 2048];      // 16 MB  fragB order, K=2048 (d>=2048)
__device__ __half g_W2t[1024 * 4096];       //  8 MB  fragB order, K=4096
__device__ float  g_A0p[4 * 256 * 4096];    // 16 MB  split-K partials (row-major)
__device__ float  g_Cp[4][16 * 4096];       //  1 MB  v-term l-partials (row-major)
__device__ __half g_hsum[256 * 4096];       //  2 MB  fragA order, K=4096
__device__ float  g_etap[8 * 256 * 1024];   //  8 MB  split-K partials (row-major)
// chain counters + work queue head (reset by prep_all block 0 each replay)
__device__ int    c_g0;
__device__ int    c_g1g[8];
__device__ int    c_g2;
__device__ int    c_next;

#define N_ITEMS 1664
#define N_CTAS  592

__device__ __forceinline__ uint32_t smem_u32(const void* p) {
    uint32_t a;
    asm("{ .reg .u64 t; cvta.to.shared.u64 t, %1; cvt.u32.u64 %0, t; }" : "=r"(a) : "l"(p));
    return a;
}
// fragA (m16n8k16 f16 A): 16x16 tile = 256 halves; lane t owns halves [t*8 .. t*8+7]
__device__ __forceinline__ size_t fragA_half(int r, int k, int K) {
    size_t blk = (size_t)(r >> 4) * (K >> 4) + (k >> 4);
    int lane = (r & 7) * 4 + ((k & 7) >> 1);
    int reg  = ((k & 8) >> 2) | ((r & 8) >> 3);
    return blk * 256 + (size_t)((lane * 4 + reg) * 2 + (k & 1));
}
#define CP16(dst, src) \
    asm volatile("cp.async.cg.shared.global [%0], [%1], 16;\n" :: "r"(dst), "l"(src))

#define A_STAGE_B 16384
#define B_STAGE_B 16384
#define STAGE_B (A_STAGE_B + B_STAGE_B)
#define GEMM_SMEM (3 * STAGE_B)        // 96 KB

#define MMA16(acc, af, b0v, b1v)                                               \
    asm volatile(                                                              \
        "mma.sync.aligned.m16n8k16.row.col.f32.f16.f16.f32 "                   \
        "{%0,%1,%2,%3}, {%4,%5,%6,%7}, {%8,%9}, {%0,%1,%2,%3};"                \
        : "+f"(acc[0]), "+f"(acc[1]), "+f"(acc[2]), "+f"(acc[3])               \
        : "r"(af.x), "r"(af.y), "r"(af.z), "r"(af.w), "r"(b0v), "r"(b1v))

#define SPIN_GE(ctr, target) do {                                              \
    if (threadIdx.x == 0) {                                                    \
        int v_;                                                                \
        do {                                                                   \
            asm volatile("ld.global.acquire.gpu.b32 %0, [%1];"                 \
                         : "=r"(v_) : "l"(&(ctr)));                            \
        } while (v_ < (target));                                               \
    }                                                                          \
    __syncthreads();                                                           \
} while (0)

#define DONE_ADD(ctr) do {                                                     \
    __syncthreads();                                                           \
    if (threadIdx.x == 0) { __threadfence(); atomicAdd(&(ctr), 1); }           \
} while (0)

// shared GEMM mainloop: acc += A[tile rt0..+8][K] @ Bt[tile ct0..+8][K]^T
__device__ __forceinline__ void gemm_main(
    const __half* __restrict__ A, const __half* __restrict__ Bt,
    int K16a, int K16b, int rt0, int ct0, int kt0, int nchunks,
    char* smc, float acc[4][4][4]) {
    const int tid = threadIdx.x;
    const uint32_t smaddr = smem_u32(smc);

    auto load_chunk = [&](int c, int s) {
        uint32_t abase = smaddr + s * STAGE_B;
        uint32_t bbase = abase + A_STAGE_B;
        int kt = kt0 + c * 4;
#pragma unroll
        for (int i = 0; i < 4; i++) {
            int idx = tid + i * 256;
            int blk = idx >> 5, w = idx & 31;
            const __half* srcp =
                A + ((size_t)(rt0 + (blk >> 2)) * K16a + kt + (blk & 3)) * 256 + w * 8;
            CP16(abase + idx * 16, srcp);
        }
#pragma unroll
        for (int i = 0; i < 4; i++) {
            int idx = tid + i * 256;
            int blk = idx >> 5, w = idx & 31;
            const __half* srcp =
                Bt + ((size_t)(ct0 + (blk >> 2)) * K16b + kt + (blk & 3)) * 256 + w * 8;
            CP16(bbase + idx * 16, srcp);
        }
        asm volatile("cp.async.commit_group;\n");
    };

    const int wid = tid >> 5, lane = tid & 31;
    const int wm = wid & 1, wn = wid >> 1;

    load_chunk(0, 0);
    load_chunk(1, 1);

    for (int c = 0; c < nchunks; c++) {
        if (c + 1 < nchunks) asm volatile("cp.async.wait_group 1;\n");
        else                 asm volatile("cp.async.wait_group 0;\n");
        __syncthreads();
        if (c + 2 < nchunks) load_chunk(c + 2, (c + 2) % 3);

        const uint4* sA = (const uint4*)(smc + (c % 3) * STAGE_B);
        const uint4* sB = (const uint4*)(smc + (c % 3) * STAGE_B + A_STAGE_B);
#pragma unroll
        for (int ks = 0; ks < 4; ks++) {
            uint4 af[4], bq[2];
#pragma unroll
            for (int mi = 0; mi < 4; mi++)
                af[mi] = sA[(((wm * 4 + mi) * 4 + ks) << 5) + lane];
#pragma unroll
            for (int n2 = 0; n2 < 2; n2++)
                bq[n2] = sB[(((wn * 2 + n2) * 4 + ks) << 5) + lane];
#pragma unroll
            for (int mi = 0; mi < 4; mi++)
#pragma unroll
                for (int n2 = 0; n2 < 2; n2++) {
                    MMA16(acc[mi][n2 * 2],     af[mi], bq[n2].x, bq[n2].y);
                    MMA16(acc[mi][n2 * 2 + 1], af[mi], bq[n2].z, bq[n2].w);
                }
        }
    }
}

// ======================= persistent mega: dynamic work queue ===================
// items: [0,256) gemm0 | [256,1280) gemm1 | [1280,1408) gemm2 | [1408,1664) final
__global__ void __launch_bounds__(256, 2)
mega(const float* __restrict__ b1, const float* __restrict__ phi,
     const float* __restrict__ b2, float* __restrict__ out) {
    extern __shared__ char smc[];
    __shared__ int s_item;
    const int tid = threadIdx.x;
    const int wid = tid >> 5, lane = tid & 31;
    const int wm = wid & 1, wn = wid >> 1;
    const int tg = lane >> 2, tir = lane & 3;

    for (;;) {
        __syncthreads();                         // protect s_item reuse
        if (tid == 0) s_item = atomicAdd(&c_next, 1);
        __syncthreads();
        const int item = s_item;
        if (item >= N_ITEMS) break;

        if (item >= 1408) {
            // ---- finalize: out = phi - (sum_z etap + 16*b2) ----
            SPIN_GE(c_g2, 128);
            int base = (item - 1408) * 1024 + tid;
#pragma unroll
            for (int j = 0; j < 4; j++) {
                int i = base + j * 256;
                float s = 0.f;
#pragma unroll
                for (int zz = 0; zz < 8; zz++)
                    s += g_etap[(size_t)zz * (256 * 1024) + i];
                out[i] = phi[i] - (s + 16.0f * b2[i & 1023]);
            }
            continue;
        }

        float acc[4][4][4];
#pragma unroll
        for (int mi = 0; mi < 4; mi++)
#pragma unroll
            for (int ni = 0; ni < 4; ni++)
#pragma unroll
                for (int q = 0; q < 4; q++) acc[mi][ni][q] = 0.f;

        if (item < 256) {
            // ---- gemm0: A0p[z] = S @ W1tA (split-K=4) ----
            int zsp = item >> 6;
            int row0 = ((item >> 5) & 1) * 128, col0 = (item & 31) * 128;
            gemm_main(g_S, g_W1tA, 128, 128, row0 >> 4, col0 >> 4, zsp * 32, 8, smc, acc);
            float* Dz = g_A0p + (size_t)zsp * (256 * 4096);
#pragma unroll
            for (int mi = 0; mi < 4; mi++) {
                int r1 = row0 + wm * 64 + mi * 16 + tg;
#pragma unroll
                for (int ni = 0; ni < 4; ni++) {
                    int cc = col0 + wn * 32 + ni * 8 + tir * 2;
                    *(float2*)(Dz + (size_t)r1 * HH + cc) =
                        make_float2(acc[mi][ni][0], acc[mi][ni][1]);
                    *(float2*)(Dz + (size_t)(r1 + 8) * HH + cc) =
                        make_float2(acc[mi][ni][2], acc[mi][ni][3]);
                }
            }
            DONE_ADD(c_g0);
        } else if (item < 1280) {
            // ---- gemm1: hsum = sum_m relu(Wcat@W1tB + b1 + sumA0p + sumCp) ----
            int idx = item - 256;
            int row0 = (idx >> 5) * 128, col0 = (idx & 31) * 128;
            int rt0 = row0 >> 4;
            gemm_main(g_Wcat, g_W1tB, 128, 128, rt0, col0 >> 4, 0, 32, smc, acc);

            SPIN_GE(c_g0, 256);                  // A0p ready

            // CTA-cooperative staging: A0s[8][128] then Cs[16][128] in smem
            float* sE = (float*)smc;
#pragma unroll
            for (int i = 0; i < 4; i++) {
                int e = tid + i * 256;
                int bbl = e >> 7, c = e & 127;
                float v = b1[col0 + c];
#pragma unroll
                for (int zz = 0; zz < 4; zz++)
                    v += g_A0p[(size_t)zz * (256 * 4096)
                               + (size_t)(rt0 + bbl) * HH + col0 + c];
                sE[e] = v;
            }
#pragma unroll
            for (int i = 0; i < 8; i++) {
                int e = tid + i * 256;
                int m = e >> 7, c = e & 127;
                float v = 0.f;
#pragma unroll
                for (int zz = 0; zz < 4; zz++)
                    v += g_Cp[zz][(size_t)m * HH + col0 + c];
                sE[1024 + e] = v;
            }
            __syncthreads();

            const int m1 = tg, m2 = tg + 8;
#pragma unroll
            for (int mi = 0; mi < 4; mi++) {
                int bbl = wm * 4 + mi;
                int b = rt0 + bbl;
#pragma unroll
                for (int ni = 0; ni < 4; ni++) {
                    int ccl = wn * 32 + ni * 8 + tir * 2;
                    float a0x = sE[bbl * 128 + ccl], a0y = sE[bbl * 128 + ccl + 1];
                    float c1x = sE[1024 + m1 * 128 + ccl];
                    float c1y = sE[1024 + m1 * 128 + ccl + 1];
                    float c2x = sE[1024 + m2 * 128 + ccl];
                    float c2y = sE[1024 + m2 * 128 + ccl + 1];
                    float p0 = fmaxf(acc[mi][ni][0] + a0x + c1x, 0.f)
                             + fmaxf(acc[mi][ni][2] + a0x + c2x, 0.f);
                    float p1 = fmaxf(acc[mi][ni][1] + a0y + c1y, 0.f)
                             + fmaxf(acc[mi][ni][3] + a0y + c2y, 0.f);
                    p0 += __shfl_down_sync(0xffffffffu, p0, 4);
                    p0 += __shfl_down_sync(0xffffffffu, p0, 8);
                    p0 += __shfl_down_sync(0xffffffffu, p0, 16);
                    p1 += __shfl_down_sync(0xffffffffu, p1, 4);
                    p1 += __shfl_down_sync(0xffffffffu, p1, 8);
                    p1 += __shfl_down_sync(0xffffffffu, p1, 16);
                    if (tg == 0) {
                        size_t hi = fragA_half(b, col0 + ccl, HH);
                        *(__half2*)(&g_hsum[hi]) = __floats2half2_rn(p0, p1);
                    }
                }
            }
            DONE_ADD(c_g1g[(idx & 31) >> 2]);    // column group = col0/512
        } else {
            // ---- gemm2: etap[z] = hsum[:, z*512..] @ W2t[:, z*512..] ----
            int idx = item - 1280;
            int col0 = (idx & 7) * 128, row0 = ((idx >> 3) & 1) * 128;
            int z = idx >> 4;
            SPIN_GE(c_g1g[z], 128);              // this k-slice of hsum ready
            gemm_main(g_hsum, g_W2t, 256, 256, row0 >> 4, col0 >> 4, z * 32, 8, smc, acc);
            float* Dz = g_etap + (size_t)z * (256 * 1024);
#pragma unroll
            for (int mi = 0; mi < 4; mi++) {
                int r1 = row0 + wm * 64 + mi * 16 + tg;
#pragma unroll
                for (int ni = 0; ni < 4; ni++) {
                    int cc = col0 + wn * 32 + ni * 8 + tir * 2;
                    *(float2*)(Dz + (size_t)r1 * 1024 + cc) =
                        make_float2(acc[mi][ni][0], acc[mi][ni][1]);
                    *(float2*)(Dz + (size_t)(r1 + 8) * 1024 + cc) =
                        make_float2(acc[mi][ni][2], acc[mi][ni][3]);
                }
            }
            DONE_ADD(c_g2);
        }
    }
}

// ======================= fused prep (compute_C first, counter reset) ===========
// bids: [0,64) Cp | [64,1088) prep_s | [1088,9280) transpose_w
//       [9280,17472) W1 fragB | [17472,19520) W2 fragB
#define PREP_BLOCKS 19520

__global__ void __launch_bounds__(256)
prep_all(const float* __restrict__ phi,
         const float* __restrict__ wr, const float* __restrict__ wi,
         const float* __restrict__ vM,
         const float* __restrict__ W1, const float* __restrict__ W2) {
    __shared__ float sm[64 * 33];
    const int bid = blockIdx.x;
    const int tid = threadIdx.x;

    if (bid == 0 && tid == 0) {                  // reset chain counters + queue
        c_g0 = 0;
#pragma unroll
        for (int i = 0; i < 8; i++) c_g1g[i] = 0;
        c_g2 = 0;
        c_next = 0;
    }

    if (bid < 64) {
        // ---- compute_C partials (long blocks first) ----
        int hb = bid & 15, lc = bid >> 4;
        int l0 = lc * 128;
#pragma unroll
        for (int i = 0; i < 8; i++) sm[tid + i * 256] = vM[l0 * 16 + tid + i * 256];
        __syncthreads();
        int h = hb * 256 + tid;
        float acc[16];
#pragma unroll
        for (int m = 0; m < 16; m++) acc[m] = 0.f;
        const float* wp = W1 + (size_t)(4096 + l0) * HH + h;
        for (int l = 0; l < 128; l++) {
            float wv = wp[(size_t)l * HH];
#pragma unroll
            for (int m = 0; m < 16; m++) acc[m] = fmaf(sm[l * 16 + m], wv, acc[m]);
        }
#pragma unroll
        for (int m = 0; m < 16; m++) g_Cp[lc][m * HH + h] = acc[m];
    } else if (bid < 1088) {
        // ---- prep_s ----
        int i = (bid - 64) * 256 + tid;
        int b = i >> 10, l = i & 1023;
        float sv, cv;
        sincosf(phi[i], &sv, &cv);
        const float mag = 0.03125f;
        g_S[fragA_half(b, l, 2048)]        = __float2half_rn(mag * cv);
        g_S[fragA_half(b, 1024 + l, 2048)] = __float2half_rn(mag * sv);
    } else if (bid < 9280) {
        // ---- transpose_w -> g_Wcat fragA ----
        int idx = bid - 1088;
        int zb = idx >> 12;
        int rem = idx & 4095;
        int b = rem >> 4, l0 = (rem & 15) * 64;
        const float* src = zb ? wi : wr;
        int colbase = zb ? 1024 : 0;
        float (*s)[17] = (float(*)[17])sm;
        const float* sp = src + (size_t)b * 16384 + (size_t)l0 * 16;
#pragma unroll
        for (int i = 0; i < 4; i++) {
            int e = tid + i * 256;
            s[e >> 4][e & 15] = sp[e];
        }
        __syncthreads();
        int kt = tid >> 6, q0 = (tid & 63) * 2;
        uint32_t wv[2];
#pragma unroll
        for (int j = 0; j < 2; j++) {
            int q = q0 + j;
            int ln = q >> 2, rg = q & 3;
            int m = (ln >> 2) | ((rg & 1) << 3);
            int kl = kt * 16 + ((rg & 2) << 2) + (ln & 3) * 2;
            __half2 h = __floats2half2_rn(s[kl][m], s[kl + 1][m]);
            wv[j] = *(uint32_t*)&h;
        }
        uint32_t* dst = (uint32_t*)g_Wcat
            + ((size_t)b * 128 + (size_t)((colbase + l0) >> 4) + kt) * 128 + q0;
        *(uint2*)dst = make_uint2(wv[0], wv[1]);
    } else {
        // ---- fragB transposes (W1 halves, W2) ----
        const float* src; __half* dst; int Csrc, Kfrag, h0, d0, kbase;
        if (bid < 17472) {
            int idx = bid - 9280;
            int half = idx >> 12;
            int rem = idx & 4095;
            h0 = (rem & 127) * 32;
            kbase = half * 2048;
            d0 = kbase + (rem >> 7) * 64;
            src = W1; Csrc = 4096; Kfrag = 2048;
            dst = half ? g_W1tB : g_W1tA;
        } else {
            int idx = bid - 17472;
            h0 = (idx & 31) * 32;
            kbase = 0;
            d0 = (idx >> 5) * 64;
            src = W2; Csrc = 1024; Kfrag = 4096;
            dst = g_W2t;
        }
        float (*tt)[33] = (float(*)[33])sm;
        int hl = tid & 31, dl0 = tid >> 5;
#pragma unroll
        for (int i = 0; i < 8; i++)
            tt[dl0 + i * 8][hl] = src[(size_t)(d0 + dl0 + i * 8) * Csrc + h0 + hl];
        __syncthreads();
        int blk = tid >> 5, ln = tid & 31;
        int ht = blk >> 2, kt = blk & 3;
        uint32_t wv[4];
#pragma unroll
        for (int nt = 0; nt < 2; nt++)
#pragma unroll
            for (int rg = 0; rg < 2; rg++) {
                int n = ht * 16 + nt * 8 + (ln >> 2);
                int k = kt * 16 + rg * 8 + (ln & 3) * 2;
                __half2 h = __floats2half2_rn(tt[k][n], tt[k + 1][n]);
                wv[nt * 2 + rg] = *(uint32_t*)&h;
            }
        uint4* dp = (uint4*)dst
            + ((size_t)((h0 >> 4) + ht) * (Kfrag >> 4)
               + (size_t)((d0 - kbase) >> 4) + kt) * 32 + ln;
        *dp = make_uint4(wv[0], wv[1], wv[2], wv[3]);
    }
}

// ======================= launch =======================
extern "C" void kernel_launch(void* const* d_in, const int* in_sizes, int n_in,
                              void* d_out, int out_size) {
    const float* phi = (const float*)d_in[0];
    const float* wr  = (const float*)d_in[1];
    const float* wi  = (const float*)d_in[2];
    const float* vM  = (const float*)d_in[3];
    const float* W1  = (const float*)d_in[4];
    const float* b1  = (const float*)d_in[5];
    const float* W2  = (const float*)d_in[6];
    const float* b2  = (const float*)d_in[7];
    float* out = (float*)d_out;

    cudaFuncSetAttribute(mega, cudaFuncAttributeMaxDynamicSharedMemorySize, GEMM_SMEM);

    // 1) all independent producers in one launch (compute_C scheduled first)
    prep_all<<<PREP_BLOCKS, 256>>>(phi, wr, wi, vM, W1, W2);

    // 2) persistent gemm0+gemm1+gemm2+finalize: 592 CTAs (2/SM), dynamic queue
    mega<<<N_CTAS, 256, GEMM_SMEM>>>(b1, phi, b2, out);
}

// round 14
// speedup vs baseline: 1.2460x; 1.2460x over previous
#include <cuda_runtime.h>
#include <cuda_fp16.h>
#include <cstdint>
#include <math.h>

#define HH 4096

// ---------------- scratch ----------------
__device__ __half g_S[256 * 2048];          //  1 MB  fragA order, K=2048
__device__ __half g_Wcat[4096 * 2048];      // 16 MB  fragA order, K=2048
__device__ __half g_W1tA[4096 * 2048];      // 16 MB  fragB order, K=2048 (d<2048)
__device__ __half g_W1tB[4096 * 2048];      // 16 MB  fragB order, K=2048 (d>=2048)
__device__ __half g_W2t[1024 * 4096];       //  8 MB  fragB order, K=4096
__device__ float  g_A0p[4 * 256 * 4096];    // 16 MB  split-K partials (row-major)
__device__ float  g_Cp[4][16 * 4096];       //  1 MB  v-term l-partials (row-major)
__device__ __half g_hsum[256 * 4096];       //  2 MB  fragA order, K=4096
__device__ float  g_etap[8 * 256 * 1024];   //  8 MB  split-K partials (row-major)
// chain counters (reset by prep_all block 0 each replay)
__device__ int    c_g0;
__device__ int    c_g1g[8];
__device__ int    c_g2;

__device__ __forceinline__ uint32_t smem_u32(const void* p) {
    uint32_t a;
    asm("{ .reg .u64 t; cvta.to.shared.u64 t, %1; cvt.u32.u64 %0, t; }" : "=r"(a) : "l"(p));
    return a;
}
// fragA (m16n8k16 f16 A): 16x16 tile = 256 halves; lane t owns halves [t*8 .. t*8+7]
__device__ __forceinline__ size_t fragA_half(int r, int k, int K) {
    size_t blk = (size_t)(r >> 4) * (K >> 4) + (k >> 4);
    int lane = (r & 7) * 4 + ((k & 7) >> 1);
    int reg  = ((k & 8) >> 2) | ((r & 8) >> 3);
    return blk * 256 + (size_t)((lane * 4 + reg) * 2 + (k & 1));
}
#define CP16(dst, src) \
    asm volatile("cp.async.cg.shared.global [%0], [%1], 16;\n" :: "r"(dst), "l"(src))

#define A_STAGE_B 16384
#define B_STAGE_B 16384
#define STAGE_B (A_STAGE_B + B_STAGE_B)
#define GEMM_SMEM (3 * STAGE_B)        // 96 KB

#define MMA16(acc, af, b0v, b1v)                                               \
    asm volatile(                                                              \
        "mma.sync.aligned.m16n8k16.row.col.f32.f16.f16.f32 "                   \
        "{%0,%1,%2,%3}, {%4,%5,%6,%7}, {%8,%9}, {%0,%1,%2,%3};"                \
        : "+f"(acc[0]), "+f"(acc[1]), "+f"(acc[2]), "+f"(acc[3])               \
        : "r"(af.x), "r"(af.y), "r"(af.z), "r"(af.w), "r"(b0v), "r"(b1v))

#define SPIN_GE(ctr, target) do {                                              \
    if (threadIdx.x == 0) {                                                    \
        int v_;                                                                \
        do {                                                                   \
            asm volatile("ld.global.acquire.gpu.b32 %0, [%1];"                 \
                         : "=r"(v_) : "l"(&(ctr)));                            \
        } while (v_ < (target));                                               \
    }                                                                          \
    __syncthreads();                                                           \
} while (0)

#define DONE_ADD(ctr) do {                                                     \
    __syncthreads();                                                           \
    if (threadIdx.x == 0) { __threadfence(); atomicAdd(&(ctr), 1); }           \
} while (0)

// shared GEMM mainloop: acc += A[tile rt0..+8][K] @ Bt[tile ct0..+8][K]^T
__device__ __forceinline__ void gemm_main(
    const __half* __restrict__ A, const __half* __restrict__ Bt,
    int K16a, int K16b, int rt0, int ct0, int kt0, int nchunks,
    char* smc, float acc[4][4][4]) {
    const int tid = threadIdx.x;
    const uint32_t smaddr = smem_u32(smc);

    auto load_chunk = [&](int c, int s) {
        uint32_t abase = smaddr + s * STAGE_B;
        uint32_t bbase = abase + A_STAGE_B;
        int kt = kt0 + c * 4;
#pragma unroll
        for (int i = 0; i < 4; i++) {
            int idx = tid + i * 256;
            int blk = idx >> 5, w = idx & 31;
            const __half* srcp =
                A + ((size_t)(rt0 + (blk >> 2)) * K16a + kt + (blk & 3)) * 256 + w * 8;
            CP16(abase + idx * 16, srcp);
        }
#pragma unroll
        for (int i = 0; i < 4; i++) {
            int idx = tid + i * 256;
            int blk = idx >> 5, w = idx & 31;
            const __half* srcp =
                Bt + ((size_t)(ct0 + (blk >> 2)) * K16b + kt + (blk & 3)) * 256 + w * 8;
            CP16(bbase + idx * 16, srcp);
        }
        asm volatile("cp.async.commit_group;\n");
    };

    const int wid = tid >> 5, lane = tid & 31;
    const int wm = wid & 1, wn = wid >> 1;

    load_chunk(0, 0);
    load_chunk(1, 1);

    for (int c = 0; c < nchunks; c++) {
        if (c + 1 < nchunks) asm volatile("cp.async.wait_group 1;\n");
        else                 asm volatile("cp.async.wait_group 0;\n");
        __syncthreads();
        if (c + 2 < nchunks) load_chunk(c + 2, (c + 2) % 3);

        const uint4* sA = (const uint4*)(smc + (c % 3) * STAGE_B);
        const uint4* sB = (const uint4*)(smc + (c % 3) * STAGE_B + A_STAGE_B);
#pragma unroll
        for (int ks = 0; ks < 4; ks++) {
            uint4 af[4], bq[2];
#pragma unroll
            for (int mi = 0; mi < 4; mi++)
                af[mi] = sA[(((wm * 4 + mi) * 4 + ks) << 5) + lane];
#pragma unroll
            for (int n2 = 0; n2 < 2; n2++)
                bq[n2] = sB[(((wn * 2 + n2) * 4 + ks) << 5) + lane];
#pragma unroll
            for (int mi = 0; mi < 4; mi++)
#pragma unroll
                for (int n2 = 0; n2 < 2; n2++) {
                    MMA16(acc[mi][n2 * 2],     af[mi], bq[n2].x, bq[n2].y);
                    MMA16(acc[mi][n2 * 2 + 1], af[mi], bq[n2].z, bq[n2].w);
                }
        }
    }
}

// ======================= mega: gemm0 + gemm1 + gemm2 + finalize ================
// bids: [0,256) gemm0 | [256,1280) gemm1 (COLUMN-major: col-group z contiguous)
//       [1280,1408) gemm2 | [1408,1664) finalize
__global__ void __launch_bounds__(256, 2)
mega(const float* __restrict__ b1, const float* __restrict__ phi,
     const float* __restrict__ b2, float* __restrict__ out) {
    extern __shared__ char smc[];
    const int tid = threadIdx.x;
    const int bid = blockIdx.x;
    const int wid = tid >> 5, lane = tid & 31;
    const int wm = wid & 1, wn = wid >> 1;
    const int tg = lane >> 2, tir = lane & 3;

    if (bid >= 1408) {
        // ---- finalize: out = phi - (sum_z etap + 16*b2) ----
        SPIN_GE(c_g2, 128);
        int base = (bid - 1408) * 1024 + tid;
#pragma unroll
        for (int j = 0; j < 4; j++) {
            int i = base + j * 256;
            float s = 0.f;
#pragma unroll
            for (int zz = 0; zz < 8; zz++) s += g_etap[(size_t)zz * (256 * 1024) + i];
            out[i] = phi[i] - (s + 16.0f * b2[i & 1023]);
        }
        return;
    }

    float acc[4][4][4];
#pragma unroll
    for (int mi = 0; mi < 4; mi++)
#pragma unroll
        for (int ni = 0; ni < 4; ni++)
#pragma unroll
            for (int q = 0; q < 4; q++) acc[mi][ni][q] = 0.f;

    if (bid < 256) {
        // ---- gemm0: A0p[z] = S @ W1tA (split-K=4) ----
        int zsp = bid >> 6;
        int row0 = ((bid >> 5) & 1) * 128, col0 = (bid & 31) * 128;
        gemm_main(g_S, g_W1tA, 128, 128, row0 >> 4, col0 >> 4, zsp * 32, 8, smc, acc);
        float* Dz = g_A0p + (size_t)zsp * (256 * 4096);
#pragma unroll
        for (int mi = 0; mi < 4; mi++) {
            int r1 = row0 + wm * 64 + mi * 16 + tg;
#pragma unroll
            for (int ni = 0; ni < 4; ni++) {
                int cc = col0 + wn * 32 + ni * 8 + tir * 2;
                *(float2*)(Dz + (size_t)r1 * HH + cc) =
                    make_float2(acc[mi][ni][0], acc[mi][ni][1]);
                *(float2*)(Dz + (size_t)(r1 + 8) * HH + cc) =
                    make_float2(acc[mi][ni][2], acc[mi][ni][3]);
            }
        }
        DONE_ADD(c_g0);
    } else if (bid < 1280) {
        // ---- gemm1 (column-major): col = idx>>5, row = idx&31 ----
        int idx = bid - 256;
        int col0 = (idx >> 5) * 128, row0 = (idx & 31) * 128;
        int rt0 = row0 >> 4;
        gemm_main(g_Wcat, g_W1tB, 128, 128, rt0, col0 >> 4, 0, 32, smc, acc);

        SPIN_GE(c_g0, 256);                      // A0p ready

        // CTA-cooperative staging: A0s[8][128] then Cs[16][128] in smem
        float* sE = (float*)smc;
#pragma unroll
        for (int i = 0; i < 4; i++) {
            int e = tid + i * 256;
            int bbl = e >> 7, c = e & 127;
            float v = b1[col0 + c];
#pragma unroll
            for (int zz = 0; zz < 4; zz++)
                v += g_A0p[(size_t)zz * (256 * 4096) + (size_t)(rt0 + bbl) * HH + col0 + c];
            sE[e] = v;
        }
#pragma unroll
        for (int i = 0; i < 8; i++) {
            int e = tid + i * 256;
            int m = e >> 7, c = e & 127;
            float v = 0.f;
#pragma unroll
            for (int zz = 0; zz < 4; zz++)
                v += g_Cp[zz][(size_t)m * HH + col0 + c];
            sE[1024 + e] = v;
        }
        __syncthreads();

        const int m1 = tg, m2 = tg + 8;
#pragma unroll
        for (int mi = 0; mi < 4; mi++) {
            int bbl = wm * 4 + mi;
            int b = rt0 + bbl;
#pragma unroll
            for (int ni = 0; ni < 4; ni++) {
                int ccl = wn * 32 + ni * 8 + tir * 2;
                float a0x = sE[bbl * 128 + ccl], a0y = sE[bbl * 128 + ccl + 1];
                float c1x = sE[1024 + m1 * 128 + ccl], c1y = sE[1024 + m1 * 128 + ccl + 1];
                float c2x = sE[1024 + m2 * 128 + ccl], c2y = sE[1024 + m2 * 128 + ccl + 1];
                float p0 = fmaxf(acc[mi][ni][0] + a0x + c1x, 0.f)
                         + fmaxf(acc[mi][ni][2] + a0x + c2x, 0.f);
                float p1 = fmaxf(acc[mi][ni][1] + a0y + c1y, 0.f)
                         + fmaxf(acc[mi][ni][3] + a0y + c2y, 0.f);
                p0 += __shfl_down_sync(0xffffffffu, p0, 4);
                p0 += __shfl_down_sync(0xffffffffu, p0, 8);
                p0 += __shfl_down_sync(0xffffffffu, p0, 16);
                p1 += __shfl_down_sync(0xffffffffu, p1, 4);
                p1 += __shfl_down_sync(0xffffffffu, p1, 8);
                p1 += __shfl_down_sync(0xffffffffu, p1, 16);
                if (tg == 0) {
                    size_t hi = fragA_half(b, col0 + ccl, HH);
                    *(__half2*)(&g_hsum[hi]) = __floats2half2_rn(p0, p1);
                }
            }
        }
        DONE_ADD(c_g1g[idx >> 7]);               // column group = 128 contiguous bids
    } else {
        // ---- gemm2: etap[z] = hsum[:, z*512..] @ W2t[:, z*512..] ----
        int idx = bid - 1280;
        int z = idx >> 4;
        int col0 = (idx & 7) * 128, row0 = ((idx >> 3) & 1) * 128;
        SPIN_GE(c_g1g[z], 128);                  // this k-slice of hsum ready
        gemm_main(g_hsum, g_W2t, 256, 256, row0 >> 4, col0 >> 4, z * 32, 8, smc, acc);
        float* Dz = g_etap + (size_t)z * (256 * 1024);
#pragma unroll
        for (int mi = 0; mi < 4; mi++) {
            int r1 = row0 + wm * 64 + mi * 16 + tg;
#pragma unroll
            for (int ni = 0; ni < 4; ni++) {
                int cc = col0 + wn * 32 + ni * 8 + tir * 2;
                *(float2*)(Dz + (size_t)r1 * 1024 + cc) =
                    make_float2(acc[mi][ni][0], acc[mi][ni][1]);
                *(float2*)(Dz + (size_t)(r1 + 8) * 1024 + cc) =
                    make_float2(acc[mi][ni][2], acc[mi][ni][3]);
            }
        }
        DONE_ADD(c_g2);
    }
}

// ======================= fused prep (compute_C first, counter reset) ===========
// bids: [0,64) Cp | [64,1088) prep_s | [1088,9280) transpose_w
//       [9280,17472) W1 fragB | [17472,19520) W2 fragB
#define PREP_BLOCKS 19520

__global__ void __launch_bounds__(256)
prep_all(const float* __restrict__ phi,
         const float* __restrict__ wr, const float* __restrict__ wi,
         const float* __restrict__ vM,
         const float* __restrict__ W1, const float* __restrict__ W2) {
    __shared__ float sm[64 * 33];
    const int bid = blockIdx.x;
    const int tid = threadIdx.x;

    if (bid == 0 && tid == 0) {                  // reset chain counters
        c_g0 = 0;
#pragma unroll
        for (int i = 0; i < 8; i++) c_g1g[i] = 0;
        c_g2 = 0;
    }

    if (bid < 64) {
        // ---- compute_C partials (long blocks first) ----
        int hb = bid & 15, lc = bid >> 4;
        int l0 = lc * 128;
#pragma unroll
        for (int i = 0; i < 8; i++) sm[tid + i * 256] = vM[l0 * 16 + tid + i * 256];
        __syncthreads();
        int h = hb * 256 + tid;
        float acc[16];
#pragma unroll
        for (int m = 0; m < 16; m++) acc[m] = 0.f;
        const float* wp = W1 + (size_t)(4096 + l0) * HH + h;
        for (int l = 0; l < 128; l++) {
            float wv = wp[(size_t)l * HH];
#pragma unroll
            for (int m = 0; m < 16; m++) acc[m] = fmaf(sm[l * 16 + m], wv, acc[m]);
        }
#pragma unroll
        for (int m = 0; m < 16; m++) g_Cp[lc][m * HH + h] = acc[m];
    } else if (bid < 1088) {
        // ---- prep_s ----
        int i = (bid - 64) * 256 + tid;
        int b = i >> 10, l = i & 1023;
        float sv, cv;
        sincosf(phi[i], &sv, &cv);
        const float mag = 0.03125f;
        g_S[fragA_half(b, l, 2048)]        = __float2half_rn(mag * cv);
        g_S[fragA_half(b, 1024 + l, 2048)] = __float2half_rn(mag * sv);
    } else if (bid < 9280) {
        // ---- transpose_w -> g_Wcat fragA ----
        int idx = bid - 1088;
        int zb = idx >> 12;
        int rem = idx & 4095;
        int b = rem >> 4, l0 = (rem & 15) * 64;
        const float* src = zb ? wi : wr;
        int colbase = zb ? 1024 : 0;
        float (*s)[17] = (float(*)[17])sm;
        const float* sp = src + (size_t)b * 16384 + (size_t)l0 * 16;
#pragma unroll
        for (int i = 0; i < 4; i++) {
            int e = tid + i * 256;
            s[e >> 4][e & 15] = sp[e];
        }
        __syncthreads();
        int kt = tid >> 6, q0 = (tid & 63) * 2;
        uint32_t wv[2];
#pragma unroll
        for (int j = 0; j < 2; j++) {
            int q = q0 + j;
            int ln = q >> 2, rg = q & 3;
            int m = (ln >> 2) | ((rg & 1) << 3);
            int kl = kt * 16 + ((rg & 2) << 2) + (ln & 3) * 2;
            __half2 h = __floats2half2_rn(s[kl][m], s[kl + 1][m]);
            wv[j] = *(uint32_t*)&h;
        }
        uint32_t* dst = (uint32_t*)g_Wcat
            + ((size_t)b * 128 + (size_t)((colbase + l0) >> 4) + kt) * 128 + q0;
        *(uint2*)dst = make_uint2(wv[0], wv[1]);
    } else {
        // ---- fragB transposes (W1 halves, W2) ----
        const float* src; __half* dst; int Csrc, Kfrag, h0, d0, kbase;
        if (bid < 17472) {
            int idx = bid - 9280;
            int half = idx >> 12;
            int rem = idx & 4095;
            h0 = (rem & 127) * 32;
            kbase = half * 2048;
            d0 = kbase + (rem >> 7) * 64;
            src = W1; Csrc = 4096; Kfrag = 2048;
            dst = half ? g_W1tB : g_W1tA;
        } else {
            int idx = bid - 17472;
            h0 = (idx & 31) * 32;
            kbase = 0;
            d0 = (idx >> 5) * 64;
            src = W2; Csrc = 1024; Kfrag = 4096;
            dst = g_W2t;
        }
        float (*tt)[33] = (float(*)[33])sm;
        int hl = tid & 31, dl0 = tid >> 5;
#pragma unroll
        for (int i = 0; i < 8; i++)
            tt[dl0 + i * 8][hl] = src[(size_t)(d0 + dl0 + i * 8) * Csrc + h0 + hl];
        __syncthreads();
        int blk = tid >> 5, ln = tid & 31;
        int ht = blk >> 2, kt = blk & 3;
        uint32_t wv[4];
#pragma unroll
        for (int nt = 0; nt < 2; nt++)
#pragma unroll
            for (int rg = 0; rg < 2; rg++) {
                int n = ht * 16 + nt * 8 + (ln >> 2);
                int k = kt * 16 + rg * 8 + (ln & 3) * 2;
                __half2 h = __floats2half2_rn(tt[k][n], tt[k + 1][n]);
                wv[nt * 2 + rg] = *(uint32_t*)&h;
            }
        uint4* dp = (uint4*)dst
            + ((size_t)((h0 >> 4) + ht) * (Kfrag >> 4)
               + (size_t)((d0 - kbase) >> 4) + kt) * 32 + ln;
        *dp = make_uint4(wv[0], wv[1], wv[2], wv[3]);
    }
}

// ======================= launch =======================
extern "C" void kernel_launch(void* const* d_in, const int* in_sizes, int n_in,
                              void* d_out, int out_size) {
    const float* phi = (const float*)d_in[0];
    const float* wr  = (const float*)d_in[1];
    const float* wi  = (const float*)d_in[2];
    const float* vM  = (const float*)d_in[3];
    const float* W1  = (const float*)d_in[4];
    const float* b1  = (const float*)d_in[5];
    const float* W2  = (const float*)d_in[6];
    const float* b2  = (const float*)d_in[7];
    float* out = (float*)d_out;

    cudaFuncSetAttribute(mega, cudaFuncAttributeMaxDynamicSharedMemorySize, GEMM_SMEM);

    // 1) all independent producers in one launch (compute_C scheduled first)
    prep_all<<<PREP_BLOCKS, 256>>>(phi, wr, wi, vM, W1, W2);

    // 2) gemm0 + gemm1(col-major) + gemm2 + finalize, chained by counters
    mega<<<1664, 256, GEMM_SMEM>>>(b1, phi, b2, out);
}